// round 3
// baseline (speedup 1.0000x reference)
#include <cuda_runtime.h>
#include <cuda_bf16.h>
#include <cstdint>
#include <math.h>

// GRU: T=512, B=64, H=I=1024
// - x-projections: one big 3-term bf16-split GEMM (parallel, tensor pipe)
// - recurrence: ONE persistent kernel, 64 CTAs (1/SM), weights resident in
//   SMEM, software grid barrier (2 per step), cross-CTA state via L2 (.cg)

#define Tn 512
#define Bn 64
#define Hn 1024
#define In 1024
#define HIn 2048
#define Mtot (Tn * Bn)   // 32768
#define GRID_P 64

typedef __nv_bfloat16 bf16;

// ---------------- device globals (no runtime allocation allowed) ----------
__device__ __align__(256) bf16  g_Wh[6ull * Hn * Hn];     // [z hi,lo | r hi,lo | t hi,lo][n][k]
__device__ __align__(256) bf16  g_Wx[6ull * Hn * In];
__device__ __align__(256) bf16  g_xh[(size_t)Mtot * In];
__device__ __align__(256) bf16  g_xl[(size_t)Mtot * In];
__device__ __align__(256) float g_xpre[3ull * Mtot * Hn]; // x@Wx^T + b per gate
__device__ __align__(256) float g_h[Bn * Hn];
__device__ __align__(256) float g_z[Bn * Hn];
__device__ __align__(256) bf16  g_hh[Bn * Hn], g_hl[Bn * Hn];
__device__ __align__(256) bf16  g_rhh[Bn * Hn], g_rhl[Bn * Hn];
__device__ unsigned g_arrive;

// ---------------- helpers ----------------
__device__ __forceinline__ void split2(float v, bf16& hi, bf16& lo) {
    hi = __float2bfloat16(v);
    lo = __float2bfloat16(v - __bfloat162float(hi));
}
__device__ __forceinline__ void cp16(void* s, const void* g) {   // via L1 (read-once data)
    uint32_t sa = (uint32_t)__cvta_generic_to_shared(s);
    asm volatile("cp.async.ca.shared.global [%0], [%1], 16;\n" :: "r"(sa), "l"(g));
}
__device__ __forceinline__ void cp16cg(void* s, const void* g) { // bypass L1 (cross-CTA state)
    uint32_t sa = (uint32_t)__cvta_generic_to_shared(s);
    asm volatile("cp.async.cg.shared.global [%0], [%1], 16;\n" :: "r"(sa), "l"(g));
}
#define CP_COMMIT() asm volatile("cp.async.commit_group;\n")
#define CP_WAIT1()  asm volatile("cp.async.wait_group 1;\n")
#define CP_WAIT0()  asm volatile("cp.async.wait_group 0;\n")

__device__ __forceinline__ void mma16816(float* c, const uint32_t* a, const uint32_t* b) {
    asm volatile(
        "mma.sync.aligned.m16n8k16.row.col.f32.bf16.bf16.f32 "
        "{%0,%1,%2,%3}, {%4,%5,%6,%7}, {%8,%9}, {%0,%1,%2,%3};\n"
        : "+f"(c[0]), "+f"(c[1]), "+f"(c[2]), "+f"(c[3])
        : "r"(a[0]), "r"(a[1]), "r"(a[2]), "r"(a[3]), "r"(b[0]), "r"(b[1]));
}
__device__ __forceinline__ void ldsm4(uint32_t* r, const void* p) {
    uint32_t a = (uint32_t)__cvta_generic_to_shared(p);
    asm volatile("ldmatrix.sync.aligned.m8n8.x4.shared.b16 {%0,%1,%2,%3}, [%4];\n"
                 : "=r"(r[0]), "=r"(r[1]), "=r"(r[2]), "=r"(r[3]) : "r"(a));
}
__device__ __forceinline__ void ldsm2(uint32_t* r, const void* p) {
    uint32_t a = (uint32_t)__cvta_generic_to_shared(p);
    asm volatile("ldmatrix.sync.aligned.m8n8.x2.shared.b16 {%0,%1}, [%2];\n"
                 : "=r"(r[0]), "=r"(r[1]) : "r"(a));
}

// software grid barrier (all GRID_P CTAs resident: 1 CTA/SM by smem)
__device__ __forceinline__ void grid_bar(unsigned target) {
    __threadfence();
    __syncthreads();
    if (threadIdx.x == 0) {
        atomicAdd(&g_arrive, 1u);
        unsigned v;
        do {
            asm volatile("ld.volatile.global.u32 %0, [%1];" : "=r"(v) : "l"(&g_arrive));
        } while (v < target);
    }
    __syncthreads();
    __threadfence();
}

// ---------------- prep kernels ----------------
__global__ void prep_weights(const float* Wz, const float* Wr, const float* Wt) {
    int total = 3 * Hn * HIn;
    for (int i = blockIdx.x * blockDim.x + threadIdx.x; i < total; i += gridDim.x * blockDim.x) {
        int g = i / (Hn * HIn);
        int rem = i - g * (Hn * HIn);
        int n = rem / HIn, k = rem - n * HIn;
        const float* W = (g == 0) ? Wz : ((g == 1) ? Wr : Wt);
        float v = W[(size_t)n * HIn + k];
        bf16 hi, lo; split2(v, hi, lo);
        if (k < Hn) {
            g_Wh[(size_t)(g * 2)     * Hn * Hn + (size_t)n * Hn + k] = hi;
            g_Wh[(size_t)(g * 2 + 1) * Hn * Hn + (size_t)n * Hn + k] = lo;
        } else {
            int kk = k - Hn;
            g_Wx[(size_t)(g * 2)     * Hn * In + (size_t)n * In + kk] = hi;
            g_Wx[(size_t)(g * 2 + 1) * Hn * In + (size_t)n * In + kk] = lo;
        }
    }
}
__global__ void prep_x(const float* x) {
    size_t total = (size_t)Mtot * In;
    size_t stride = (size_t)gridDim.x * blockDim.x;
    for (size_t i = blockIdx.x * (size_t)blockDim.x + threadIdx.x; i < total; i += stride) {
        bf16 hi, lo; split2(x[i], hi, lo);
        g_xh[i] = hi; g_xl[i] = lo;
    }
}
__global__ void prep_h(const float* h0) {
    int i = blockIdx.x * blockDim.x + threadIdx.x;
    if (i == 0) g_arrive = 0;                 // reset barrier counter each launch/replay
    if (i < Bn * Hn) {
        float v = h0[i];
        g_h[i] = v;
        split2(v, g_hh[i], g_hl[i]);
    }
}

// ---------------- x-projection GEMM (3-term split, 128x128 tiles) ----------
#define LDS_PAD 40
__device__ __forceinline__ void ldAfrag(uint32_t* a, const bf16* As, int mb, int k0, int lane) {
    int r = lane >> 2, c2 = (lane & 3) * 2;
    a[0] = *(const uint32_t*)(As + (size_t)(mb + r)     * LDS_PAD + k0 + c2);
    a[1] = *(const uint32_t*)(As + (size_t)(mb + r + 8) * LDS_PAD + k0 + c2);
    a[2] = *(const uint32_t*)(As + (size_t)(mb + r)     * LDS_PAD + k0 + 8 + c2);
    a[3] = *(const uint32_t*)(As + (size_t)(mb + r + 8) * LDS_PAD + k0 + 8 + c2);
}
__device__ __forceinline__ void ldBfrag(uint32_t* b, const bf16* Bs, int nb, int k0, int lane) {
    int r = lane >> 2, c2 = (lane & 3) * 2;
    b[0] = *(const uint32_t*)(Bs + (size_t)(nb + r) * LDS_PAD + k0 + c2);
    b[1] = *(const uint32_t*)(Bs + (size_t)(nb + r) * LDS_PAD + k0 + 8 + c2);
}

// grid (24 = gate*8 + ntile, 256 = mtile). CTA tile 128x128, BK=32, 96 iters.
__global__ void __launch_bounds__(256) xproj_kernel(const float* bz, const float* br, const float* bt) {
    __shared__ __align__(16) bf16 sA[2][128 * LDS_PAD];
    __shared__ __align__(16) bf16 sB[2][128 * LDS_PAD];
    const int gate = blockIdx.x >> 3;
    const int n0 = (blockIdx.x & 7) * 128;
    const int m0 = blockIdx.y * 128;
    const int tid = threadIdx.x, lane = tid & 31, warp = tid >> 5;
    const int wm = (warp & 3) * 32, wn = (warp >> 2) * 64;

    float acc[2][8][4];
    #pragma unroll
    for (int i = 0; i < 2; i++)
        #pragma unroll
        for (int j = 0; j < 8; j++)
            #pragma unroll
            for (int k = 0; k < 4; k++) acc[i][j][k] = 0.f;

    auto issue = [&](int it, int buf) {
        int c = it >> 5, kk = (it & 31) * 32;     // c: 0=AhBh 1=AhBl 2=AlBh
        const bf16* Asrc = (c == 2) ? g_xl : g_xh;
        const bf16* Bsrc = g_Wx + (size_t)(gate * 2 + (c == 1)) * ((size_t)Hn * In) + (size_t)n0 * In;
        #pragma unroll
        for (int j = 0; j < 2; j++) {
            int id = tid + j * 256;
            int r = id >> 2, cg = (id & 3) * 8;
            cp16(&sA[buf][r * LDS_PAD + cg], Asrc + (size_t)(m0 + r) * In + kk + cg);
            cp16(&sB[buf][r * LDS_PAD + cg], Bsrc + (size_t)r * In + kk + cg);
        }
    };

    issue(0, 0);
    CP_COMMIT();
    for (int it = 0; it < 96; it++) {
        int buf = it & 1;
        if (it + 1 < 96) { issue(it + 1, buf ^ 1); CP_COMMIT(); CP_WAIT1(); }
        else             { CP_WAIT0(); }
        __syncthreads();
        #pragma unroll
        for (int ks = 0; ks < 32; ks += 16) {
            uint32_t af[2][4], bfr[8][2];
            #pragma unroll
            for (int mi = 0; mi < 2; mi++) ldAfrag(af[mi], &sA[buf][0], wm + mi * 16, ks, lane);
            #pragma unroll
            for (int nf = 0; nf < 8; nf++) ldBfrag(bfr[nf], &sB[buf][0], wn + nf * 8, ks, lane);
            #pragma unroll
            for (int mi = 0; mi < 2; mi++)
                #pragma unroll
                for (int nf = 0; nf < 8; nf++)
                    mma16816(acc[mi][nf], af[mi], bfr[nf]);
        }
        __syncthreads();
    }

    const float* bias = (gate == 0) ? bz : ((gate == 1) ? br : bt);
    #pragma unroll
    for (int mi = 0; mi < 2; mi++) {
        #pragma unroll
        for (int nf = 0; nf < 8; nf++) {
            int row = m0 + wm + mi * 16 + (lane >> 2);
            int col = n0 + wn + nf * 8 + (lane & 3) * 2;
            float b0v = bias[col], b1v = bias[col + 1];
            size_t base = (size_t)gate * Mtot * Hn + (size_t)row * Hn + col;
            g_xpre[base]              = acc[mi][nf][0] + b0v;
            g_xpre[base + 1]          = acc[mi][nf][1] + b1v;
            g_xpre[base + 8 * Hn]     = acc[mi][nf][2] + b0v;
            g_xpre[base + 8 * Hn + 1] = acc[mi][nf][3] + b1v;
        }
    }
}

// ---------------- persistent recurrence kernel ----------------
// 64 CTAs x 256 threads. CTA nt owns cols [nt*16, nt*16+16) of z, r, t gates.
// SMEM: sWzr [2 split][32 rows (0-15=z, 16-31=r)][1024]  = 131072 B
//       sWt  [2 split][16 rows][1024]                    =  65536 B
//       sA   [2 buf][2 split][64 rows][64 k]             =  32768 B
#define WZR_OFF 0
#define WT_OFF  131072
#define SA_OFF  196608
#define SMEM_P  229376

__global__ void __launch_bounds__(256, 1) gru_persistent(float* __restrict__ out) {
    extern __shared__ char smem[];
    const int tid = threadIdx.x, lane = tid & 31, warp = tid >> 5;
    const int nt = blockIdx.x;
    const int wm = (warp & 3) * 16;      // warp row base (M=64 over 4 warps)
    const int wsel = warp >> 2;          // 0 or 1
    const int wn1 = wsel * 16;           // phase1: 0=z-cols, 16=r-cols
    const int wn2 = wsel * 8;            // phase2: col base within 16

    // ---- load resident weights into SMEM (once) ----
    #pragma unroll
    for (int j = 0; j < 32; j++) {       // sWzr: 8192 x 16B chunks
        int id = tid + j * 256;
        int split = id >> 12, row = (id >> 7) & 31, c = id & 127;
        int gidx = (row < 16 ? 0 : 2) + split;
        const bf16* src = g_Wh + ((size_t)gidx << 20) + (size_t)(nt * 16 + (row & 15)) * 1024 + c * 8;
        int csw = (c & 0x78) | ((c ^ row) & 7);
        cp16(smem + WZR_OFF + split * 65536 + row * 2048 + csw * 16, src);
    }
    #pragma unroll
    for (int j = 0; j < 16; j++) {       // sWt: 4096 chunks
        int id = tid + j * 256;
        int split = id >> 11, row = (id >> 7) & 15, c = id & 127;
        const bf16* src = g_Wh + ((size_t)(4 + split) << 20) + (size_t)(nt * 16 + row) * 1024 + c * 8;
        int csw = (c & 0x78) | ((c ^ row) & 7);
        cp16(smem + WT_OFF + split * 32768 + row * 2048 + csw * 16, src);
    }
    CP_COMMIT(); CP_WAIT0();
    __syncthreads();

    // per-lane fragment address components
    const int arow = wm + (lane & 15);                         // A row for ldsm x4
    const int akh  = (lane >> 4) * 8;                          // A k-half
    const int bn1  = wn1 + ((lane >> 4) << 3) + (lane & 7);    // phase1 B smem row
    const int bn2  = wn2 + (lane & 7);                         // phase2 B smem row
    const int bkh  = ((lane >> 3) & 1) * 8;                    // B k-half

    // per-lane epilogue element coordinates (c-fragment layout)
    int erow[4], ecol[4];
    #pragma unroll
    for (int e = 0; e < 4; e++) {
        erow[e] = wm + (lane >> 2) + ((e >> 1) * 8);
        ecol[e] = (lane & 3) * 2 + (e & 1);
    }

    auto issueA = [&](const bf16* srcH, const bf16* srcL, int kt, int buf) {
        int k0 = kt * 64;
        #pragma unroll
        for (int j = 0; j < 4; j++) {
            int id = tid + j * 256;                            // 1024 chunks
            int split = id >> 9, r = (id >> 3) & 63, c = id & 7;
            const bf16* s = (split ? srcL : srcH) + (size_t)r * 1024 + k0 + c * 8;
            cp16cg(smem + SA_OFF + buf * 16384 + split * 8192 + r * 128 + ((c ^ (r & 7)) << 4), s);
        }
    };

    unsigned bt = 0;
    for (int t = 0; t < Tn; t++) {
        // ================= phase 1: pre_{z,r} = h @ Wzr^T =================
        float acc1[2][4];
        #pragma unroll
        for (int i = 0; i < 2; i++)
            #pragma unroll
            for (int j = 0; j < 4; j++) acc1[i][j] = 0.f;

        issueA(g_hh, g_hl, 0, 0); CP_COMMIT();

        // prefetch epilogue operands (xpre is constant; g_h ordered by prior barrier)
        float xp1[2][4], hpre[2][4];
        #pragma unroll
        for (int nf = 0; nf < 2; nf++)
            #pragma unroll
            for (int e = 0; e < 4; e++) {
                int col = nt * 16 + nf * 8 + ecol[e];
                size_t xoff = ((size_t)wsel * Mtot + (size_t)t * Bn + erow[e]) * Hn + col;
                xp1[nf][e] = g_xpre[xoff];
                hpre[nf][e] = g_h[erow[e] * Hn + col];
            }

        for (int kt = 0; kt < 16; kt++) {
            int buf = kt & 1;
            if (kt + 1 < 16) { issueA(g_hh, g_hl, kt + 1, buf ^ 1); CP_COMMIT(); CP_WAIT1(); }
            else             { CP_WAIT0(); }
            __syncthreads();
            #pragma unroll
            for (int ks = 0; ks < 4; ks++) {
                int kl = ks * 16 + akh;
                const char* pA = smem + SA_OFF + buf * 16384 + arow * 128 + ((((kl >> 3)) ^ (arow & 7)) << 4);
                uint32_t ah[4], al[4];
                ldsm4(ah, pA); ldsm4(al, pA + 8192);
                int kg = kt * 64 + ks * 16 + bkh;
                const char* pB = smem + WZR_OFF + bn1 * 2048 + (((kg >> 3) ^ (bn1 & 7)) << 4);
                uint32_t bh[4], bl[4];
                ldsm4(bh, pB); ldsm4(bl, pB + 65536);
                mma16816(acc1[0], ah, bh); mma16816(acc1[1], ah, bh + 2);
                mma16816(acc1[0], ah, bl); mma16816(acc1[1], ah, bl + 2);
                mma16816(acc1[0], al, bh); mma16816(acc1[1], al, bh + 2);
            }
            __syncthreads();
        }

        // ---- act1: z -> g_z ; r -> rh splits ----
        #pragma unroll
        for (int nf = 0; nf < 2; nf++) {
            #pragma unroll
            for (int e = 0; e < 4; e++) {
                int col = nt * 16 + nf * 8 + ecol[e];
                float pre = acc1[nf][e] + xp1[nf][e];
                float s = 1.f / (1.f + expf(-pre));
                int gi = erow[e] * Hn + col;
                if (wsel) {           // r-warps
                    float rh = s * hpre[nf][e];
                    split2(rh, g_rhh[gi], g_rhl[gi]);
                } else {              // z-warps
                    g_z[gi] = s;
                }
            }
        }
        bt += GRID_P; grid_bar(bt);

        // ================= phase 2: pre_t = (r*h) @ Wt^T =================
        float acc2[4] = {0.f, 0.f, 0.f, 0.f};
        issueA(g_rhh, g_rhl, 0, 0); CP_COMMIT();

        // prefetch epilogue operands (g_z/g_h ordered by grid_bar's syncthreads)
        float xp2[4], zpre[4], hpre2[4];
        #pragma unroll
        for (int e = 0; e < 4; e++) {
            int col = nt * 16 + wn2 + ecol[e];
            size_t xoff = (2ull * Mtot + (size_t)t * Bn + erow[e]) * Hn + col;
            xp2[e] = g_xpre[xoff];
            int gi = erow[e] * Hn + col;
            zpre[e] = g_z[gi];
            hpre2[e] = g_h[gi];
        }

        for (int kt = 0; kt < 16; kt++) {
            int buf = kt & 1;
            if (kt + 1 < 16) { issueA(g_rhh, g_rhl, kt + 1, buf ^ 1); CP_COMMIT(); CP_WAIT1(); }
            else             { CP_WAIT0(); }
            __syncthreads();
            #pragma unroll
            for (int ks = 0; ks < 4; ks++) {
                int kl = ks * 16 + akh;
                const char* pA = smem + SA_OFF + buf * 16384 + arow * 128 + ((((kl >> 3)) ^ (arow & 7)) << 4);
                uint32_t ah[4], al[4];
                ldsm4(ah, pA); ldsm4(al, pA + 8192);
                int kg = kt * 64 + ks * 16 + bkh;
                const char* pB = smem + WT_OFF + bn2 * 2048 + (((kg >> 3) ^ (bn2 & 7)) << 4);
                uint32_t bh[2], bl[2];
                ldsm2(bh, pB); ldsm2(bl, pB + 32768);
                mma16816(acc2, ah, bh);
                mma16816(acc2, ah, bl);
                mma16816(acc2, al, bh);
            }
            __syncthreads();
        }

        // ---- act2: h update + output ----
        #pragma unroll
        for (int e = 0; e < 4; e++) {
            int col = nt * 16 + wn2 + ecol[e];
            float ht = tanhf(acc2[e] + xp2[e]);
            int gi = erow[e] * Hn + col;
            float z = zpre[e];
            float hn = (1.f - z) * hpre2[e] + z * ht;
            g_h[gi] = hn;
            split2(hn, g_hh[gi], g_hl[gi]);
            out[(size_t)t * (Bn * Hn) + gi] = hn;
        }
        bt += GRID_P; grid_bar(bt);
    }
}

// ---------------- launch ----------------
extern "C" void kernel_launch(void* const* d_in, const int* in_sizes, int n_in,
                              void* d_out, int out_size) {
    const float* x    = (const float*)d_in[0];
    const float* h0   = (const float*)d_in[1];
    const float* Wz_w = (const float*)d_in[2];
    const float* Wz_b = (const float*)d_in[3];
    const float* Wr_w = (const float*)d_in[4];
    const float* Wr_b = (const float*)d_in[5];
    const float* Wt_w = (const float*)d_in[6];
    const float* Wt_b = (const float*)d_in[7];
    float* out = (float*)d_out;

    cudaFuncSetAttribute(gru_persistent, cudaFuncAttributeMaxDynamicSharedMemorySize, SMEM_P);

    prep_weights<<<3072, 256>>>(Wz_w, Wr_w, Wt_w);
    prep_x<<<8192, 256>>>(x);
    prep_h<<<(Bn * Hn + 255) / 256, 256>>>(h0);
    xproj_kernel<<<dim3(24, 256), 256>>>(Wz_b, Wr_b, Wt_b);
    gru_persistent<<<GRID_P, 256, SMEM_P>>>(out);
}

// round 4
// speedup vs baseline: 1.0773x; 1.0773x over previous
#include <cuda_runtime.h>
#include <cuda_bf16.h>
#include <cstdint>
#include <math.h>

// GRU: T=512, B=64, H=I=1024
// - x-projections: one big 3-term bf16-split GEMM (parallel, tensor pipe)
// - recurrence: ONE persistent kernel, 64 CTAs (1/SM), weights resident in
//   SMEM, software grid barrier (2/step). A-tiles (h and r*h bf16 splits) are
//   stored PRE-SWIZZLED + tile-contiguous in global and broadcast to every
//   CTA via cp.async.bulk (16KB per op) + mbarrier -> no LSU issue bottleneck.

#define Tn 512
#define Bn 64
#define Hn 1024
#define In 1024
#define HIn 2048
#define Mtot (Tn * Bn)   // 32768
#define GRID_P 64

typedef __nv_bfloat16 bf16;

// ---------------- device globals (no runtime allocation allowed) ----------
__device__ __align__(256) bf16  g_Wh[6ull * Hn * Hn];     // [z hi,lo | r hi,lo | t hi,lo][n][k]
__device__ __align__(256) bf16  g_Wx[6ull * Hn * In];
__device__ __align__(256) bf16  g_xh[(size_t)Mtot * In];
__device__ __align__(256) bf16  g_xl[(size_t)Mtot * In];
__device__ __align__(256) float g_xpre[3ull * Mtot * Hn]; // x@Wx^T + b per gate
__device__ __align__(256) float g_h[Bn * Hn];
__device__ __align__(256) float g_z[Bn * Hn];
// A tiles, pre-swizzled tile-contiguous: [16 kt][2 split][64 rows][128B swz]
__device__ __align__(256) bf16  g_A1[2 * Bn * Hn];        // h splits
__device__ __align__(256) bf16  g_A2[2 * Bn * Hn];        // (r*h) splits
__device__ unsigned g_arrive;

// byte offset of element (row, col) inside a [kt][split=0] plane of g_A1/g_A2
__device__ __forceinline__ size_t aoff(int row, int col) {
    int kt = col >> 6, cg = (col >> 3) & 7, c8 = col & 7;
    return (size_t)kt * 16384 + (size_t)row * 128 + (((cg ^ (row & 7)) << 4) + c8 * 2);
}

// ---------------- helpers ----------------
__device__ __forceinline__ void split2(float v, bf16& hi, bf16& lo) {
    hi = __float2bfloat16(v);
    lo = __float2bfloat16(v - __bfloat162float(hi));
}
__device__ __forceinline__ void cp16(void* s, const void* g) {
    uint32_t sa = (uint32_t)__cvta_generic_to_shared(s);
    asm volatile("cp.async.ca.shared.global [%0], [%1], 16;\n" :: "r"(sa), "l"(g));
}
#define CP_COMMIT() asm volatile("cp.async.commit_group;\n")
#define CP_WAIT1()  asm volatile("cp.async.wait_group 1;\n")
#define CP_WAIT0()  asm volatile("cp.async.wait_group 0;\n")

__device__ __forceinline__ void mma16816(float* c, const uint32_t* a, const uint32_t* b) {
    asm volatile(
        "mma.sync.aligned.m16n8k16.row.col.f32.bf16.bf16.f32 "
        "{%0,%1,%2,%3}, {%4,%5,%6,%7}, {%8,%9}, {%0,%1,%2,%3};\n"
        : "+f"(c[0]), "+f"(c[1]), "+f"(c[2]), "+f"(c[3])
        : "r"(a[0]), "r"(a[1]), "r"(a[2]), "r"(a[3]), "r"(b[0]), "r"(b[1]));
}
__device__ __forceinline__ void ldsm4(uint32_t* r, const void* p) {
    uint32_t a = (uint32_t)__cvta_generic_to_shared(p);
    asm volatile("ldmatrix.sync.aligned.m8n8.x4.shared.b16 {%0,%1,%2,%3}, [%4];\n"
                 : "=r"(r[0]), "=r"(r[1]), "=r"(r[2]), "=r"(r[3]) : "r"(a));
}
__device__ __forceinline__ void ldsm2(uint32_t* r, const void* p) {
    uint32_t a = (uint32_t)__cvta_generic_to_shared(p);
    asm volatile("ldmatrix.sync.aligned.m8n8.x2.shared.b16 {%0,%1}, [%2];\n"
                 : "=r"(r[0]), "=r"(r[1]) : "r"(a));
}
__device__ __forceinline__ void mbar_wait(uint32_t mbar, unsigned parity) {
    asm volatile(
        "{\n\t.reg .pred P;\n"
        "W%=:\n\tmbarrier.try_wait.parity.acquire.cta.shared::cta.b64 P, [%0], %1, 0x989680;\n"
        "\t@P bra D%=;\n"
        "\tbra W%=;\n"
        "D%=:\n\t}\n"
        :: "r"(mbar), "r"(parity) : "memory");
}

// software grid barrier (all GRID_P CTAs resident: 1 CTA/SM by smem)
__device__ __forceinline__ void grid_bar(unsigned target) {
    __threadfence();
    __syncthreads();
    if (threadIdx.x == 0) {
        atomicAdd(&g_arrive, 1u);
        unsigned v;
        do {
            asm volatile("ld.volatile.global.u32 %0, [%1];" : "=r"(v) : "l"(&g_arrive));
        } while (v < target);
    }
    __syncthreads();
    __threadfence();
}

// ---------------- prep kernels ----------------
__global__ void prep_weights(const float* Wz, const float* Wr, const float* Wt) {
    int total = 3 * Hn * HIn;
    for (int i = blockIdx.x * blockDim.x + threadIdx.x; i < total; i += gridDim.x * blockDim.x) {
        int g = i / (Hn * HIn);
        int rem = i - g * (Hn * HIn);
        int n = rem / HIn, k = rem - n * HIn;
        const float* W = (g == 0) ? Wz : ((g == 1) ? Wr : Wt);
        float v = W[(size_t)n * HIn + k];
        bf16 hi, lo; split2(v, hi, lo);
        if (k < Hn) {
            g_Wh[(size_t)(g * 2)     * Hn * Hn + (size_t)n * Hn + k] = hi;
            g_Wh[(size_t)(g * 2 + 1) * Hn * Hn + (size_t)n * Hn + k] = lo;
        } else {
            int kk = k - Hn;
            g_Wx[(size_t)(g * 2)     * Hn * In + (size_t)n * In + kk] = hi;
            g_Wx[(size_t)(g * 2 + 1) * Hn * In + (size_t)n * In + kk] = lo;
        }
    }
}
__global__ void prep_x(const float* x) {
    size_t total = (size_t)Mtot * In;
    size_t stride = (size_t)gridDim.x * blockDim.x;
    for (size_t i = blockIdx.x * (size_t)blockDim.x + threadIdx.x; i < total; i += stride) {
        bf16 hi, lo; split2(x[i], hi, lo);
        g_xh[i] = hi; g_xl[i] = lo;
    }
}
__global__ void prep_h(const float* h0) {
    int i = blockIdx.x * blockDim.x + threadIdx.x;
    if (i == 0) g_arrive = 0;                 // reset barrier counter each launch/replay
    if (i < Bn * Hn) {
        float v = h0[i];
        g_h[i] = v;
        bf16 hi, lo; split2(v, hi, lo);
        int row = i >> 10, col = i & (Hn - 1);
        char* p = (char*)g_A1 + aoff(row, col);
        *(bf16*)p = hi;
        *(bf16*)(p + 8192) = lo;
    }
}

// ---------------- x-projection GEMM (3-term split, 128x128 tiles) ----------
#define LDS_PAD 40
__device__ __forceinline__ void ldAfrag(uint32_t* a, const bf16* As, int mb, int k0, int lane) {
    int r = lane >> 2, c2 = (lane & 3) * 2;
    a[0] = *(const uint32_t*)(As + (size_t)(mb + r)     * LDS_PAD + k0 + c2);
    a[1] = *(const uint32_t*)(As + (size_t)(mb + r + 8) * LDS_PAD + k0 + c2);
    a[2] = *(const uint32_t*)(As + (size_t)(mb + r)     * LDS_PAD + k0 + 8 + c2);
    a[3] = *(const uint32_t*)(As + (size_t)(mb + r + 8) * LDS_PAD + k0 + 8 + c2);
}
__device__ __forceinline__ void ldBfrag(uint32_t* b, const bf16* Bs, int nb, int k0, int lane) {
    int r = lane >> 2, c2 = (lane & 3) * 2;
    b[0] = *(const uint32_t*)(Bs + (size_t)(nb + r) * LDS_PAD + k0 + c2);
    b[1] = *(const uint32_t*)(Bs + (size_t)(nb + r) * LDS_PAD + k0 + 8 + c2);
}

// grid (24 = gate*8 + ntile, 256 = mtile). CTA tile 128x128, BK=32, 96 iters.
__global__ void __launch_bounds__(256) xproj_kernel(const float* bz, const float* br, const float* bt) {
    __shared__ __align__(16) bf16 sA[2][128 * LDS_PAD];
    __shared__ __align__(16) bf16 sB[2][128 * LDS_PAD];
    const int gate = blockIdx.x >> 3;
    const int n0 = (blockIdx.x & 7) * 128;
    const int m0 = blockIdx.y * 128;
    const int tid = threadIdx.x, lane = tid & 31, warp = tid >> 5;
    const int wm = (warp & 3) * 32, wn = (warp >> 2) * 64;

    float acc[2][8][4];
    #pragma unroll
    for (int i = 0; i < 2; i++)
        #pragma unroll
        for (int j = 0; j < 8; j++)
            #pragma unroll
            for (int k = 0; k < 4; k++) acc[i][j][k] = 0.f;

    auto issue = [&](int it, int buf) {
        int c = it >> 5, kk = (it & 31) * 32;     // c: 0=AhBh 1=AhBl 2=AlBh
        const bf16* Asrc = (c == 2) ? g_xl : g_xh;
        const bf16* Bsrc = g_Wx + (size_t)(gate * 2 + (c == 1)) * ((size_t)Hn * In) + (size_t)n0 * In;
        #pragma unroll
        for (int j = 0; j < 2; j++) {
            int id = tid + j * 256;
            int r = id >> 2, cg = (id & 3) * 8;
            cp16(&sA[buf][r * LDS_PAD + cg], Asrc + (size_t)(m0 + r) * In + kk + cg);
            cp16(&sB[buf][r * LDS_PAD + cg], Bsrc + (size_t)r * In + kk + cg);
        }
    };

    issue(0, 0);
    CP_COMMIT();
    for (int it = 0; it < 96; it++) {
        int buf = it & 1;
        if (it + 1 < 96) { issue(it + 1, buf ^ 1); CP_COMMIT(); CP_WAIT1(); }
        else             { CP_WAIT0(); }
        __syncthreads();
        #pragma unroll
        for (int ks = 0; ks < 32; ks += 16) {
            uint32_t af[2][4], bfr[8][2];
            #pragma unroll
            for (int mi = 0; mi < 2; mi++) ldAfrag(af[mi], &sA[buf][0], wm + mi * 16, ks, lane);
            #pragma unroll
            for (int nf = 0; nf < 8; nf++) ldBfrag(bfr[nf], &sB[buf][0], wn + nf * 8, ks, lane);
            #pragma unroll
            for (int mi = 0; mi < 2; mi++)
                #pragma unroll
                for (int nf = 0; nf < 8; nf++)
                    mma16816(acc[mi][nf], af[mi], bfr[nf]);
        }
        __syncthreads();
    }

    const float* bias = (gate == 0) ? bz : ((gate == 1) ? br : bt);
    #pragma unroll
    for (int mi = 0; mi < 2; mi++) {
        #pragma unroll
        for (int nf = 0; nf < 8; nf++) {
            int row = m0 + wm + mi * 16 + (lane >> 2);
            int col = n0 + wn + nf * 8 + (lane & 3) * 2;
            float b0v = bias[col], b1v = bias[col + 1];
            size_t base = (size_t)gate * Mtot * Hn + (size_t)row * Hn + col;
            g_xpre[base]              = acc[mi][nf][0] + b0v;
            g_xpre[base + 1]          = acc[mi][nf][1] + b1v;
            g_xpre[base + 8 * Hn]     = acc[mi][nf][2] + b0v;
            g_xpre[base + 8 * Hn + 1] = acc[mi][nf][3] + b1v;
        }
    }
}

// ---------------- persistent recurrence kernel ----------------
// 64 CTAs x 256 threads. CTA nt owns cols [nt*16, nt*16+16) of z, r, t gates.
// SMEM: sWzr [2 split][32 rows (0-15=z, 16-31=r)][1024]  = 131072 B
//       sWt  [2 split][16 rows][1024]                    =  65536 B
//       sA   [2 buf][2 split][64 rows][64 k]             =  32768 B
//       mbar [2]                                         =     16 B
#define WZR_OFF 0
#define WT_OFF  131072
#define SA_OFF  196608
#define MB_OFF  229376
#define SMEM_P  229440

__global__ void __launch_bounds__(256, 1) gru_persistent(float* __restrict__ out) {
    extern __shared__ char smem[];
    const int tid = threadIdx.x, lane = tid & 31, warp = tid >> 5;
    const int nt = blockIdx.x;
    const int wm = (warp & 3) * 16;      // warp row base (M=64 over 4 warps)
    const int wsel = warp >> 2;          // 0 or 1
    const int wn1 = wsel * 16;           // phase1: 0=z-cols, 16=r-cols
    const int wn2 = wsel * 8;            // phase2: col base within 16

    const uint32_t smem_u32 = (uint32_t)__cvta_generic_to_shared(smem);
    const uint32_t sa_u32 = smem_u32 + SA_OFF;
    const uint32_t mb_u32 = smem_u32 + MB_OFF;

    // ---- load resident weights into SMEM (once) ----
    #pragma unroll
    for (int j = 0; j < 32; j++) {       // sWzr: 8192 x 16B chunks
        int id = tid + j * 256;
        int split = id >> 12, row = (id >> 7) & 31, c = id & 127;
        int gidx = (row < 16 ? 0 : 2) + split;
        const bf16* src = g_Wh + ((size_t)gidx << 20) + (size_t)(nt * 16 + (row & 15)) * 1024 + c * 8;
        int csw = (c & 0x78) | ((c ^ row) & 7);
        cp16(smem + WZR_OFF + split * 65536 + row * 2048 + csw * 16, src);
    }
    #pragma unroll
    for (int j = 0; j < 16; j++) {       // sWt: 4096 chunks
        int id = tid + j * 256;
        int split = id >> 11, row = (id >> 7) & 15, c = id & 127;
        const bf16* src = g_Wh + ((size_t)(4 + split) << 20) + (size_t)(nt * 16 + row) * 1024 + c * 8;
        int csw = (c & 0x78) | ((c ^ row) & 7);
        cp16(smem + WT_OFF + split * 32768 + row * 2048 + csw * 16, src);
    }
    CP_COMMIT(); CP_WAIT0();
    if (tid == 0) {
        asm volatile("mbarrier.init.shared.b64 [%0], 1;" :: "r"(mb_u32) : "memory");
        asm volatile("mbarrier.init.shared.b64 [%0], 1;" :: "r"(mb_u32 + 8) : "memory");
    }
    __syncthreads();

    // per-lane fragment address components
    const int arow = wm + (lane & 15);                         // A row for ldsm x4
    const int akh  = (lane >> 4) * 8;                          // A k-half
    const int bn1  = wn1 + ((lane >> 4) << 3) + (lane & 7);    // phase1 B smem row
    const int bn2  = wn2 + (lane & 7);                         // phase2 B smem row
    const int bkh  = ((lane >> 3) & 1) * 8;                    // B k-half

    // per-lane epilogue element coordinates (c-fragment layout)
    int erow[4], ecol[4];
    #pragma unroll
    for (int e = 0; e < 4; e++) {
        erow[e] = wm + (lane >> 2) + ((e >> 1) * 8);
        ecol[e] = (lane & 3) * 2 + (e & 1);
    }

    // one 16KB bulk copy brings k-tile kt (both splits) into sA[buf]
    auto issue_tile = [&](const char* gbase, int kt, int buf) {
        if (tid == 0) {
            uint32_t mb = mb_u32 + buf * 8;
            asm volatile("mbarrier.arrive.expect_tx.shared.b64 _, [%0], %1;"
                         :: "r"(mb), "r"(16384) : "memory");
            asm volatile(
                "cp.async.bulk.shared::cluster.global.mbarrier::complete_tx::bytes [%0], [%1], %2, [%3];"
                :: "r"(sa_u32 + buf * 16384), "l"(gbase + (size_t)kt * 16384),
                   "r"(16384), "r"(mb) : "memory");
        }
    };

    unsigned p0 = 0, p1 = 0;             // mbarrier phase parity per buffer
    unsigned bt = 0;
    for (int t = 0; t < Tn; t++) {
        // ================= phase 1: pre_{z,r} = h @ Wzr^T =================
        float acc1[2][4];
        #pragma unroll
        for (int i = 0; i < 2; i++)
            #pragma unroll
            for (int j = 0; j < 4; j++) acc1[i][j] = 0.f;

        issue_tile((const char*)g_A1, 0, 0);

        // prefetch epilogue operands (xpre constant; g_h own-CTA cols)
        float xp1[2][4], hpre[2][4];
        #pragma unroll
        for (int nf = 0; nf < 2; nf++)
            #pragma unroll
            for (int e = 0; e < 4; e++) {
                int col = nt * 16 + nf * 8 + ecol[e];
                size_t xoff = ((size_t)wsel * Mtot + (size_t)t * Bn + erow[e]) * Hn + col;
                xp1[nf][e] = g_xpre[xoff];
                hpre[nf][e] = g_h[erow[e] * Hn + col];
            }

        for (int kt = 0; kt < 16; kt++) {
            int buf = kt & 1;
            if (kt + 1 < 16) issue_tile((const char*)g_A1, kt + 1, buf ^ 1);
            if (buf == 0) { mbar_wait(mb_u32, p0); p0 ^= 1; }
            else         { mbar_wait(mb_u32 + 8, p1); p1 ^= 1; }
            #pragma unroll
            for (int ks = 0; ks < 4; ks++) {
                int kl = ks * 16 + akh;
                const char* pA = smem + SA_OFF + buf * 16384 + arow * 128 + ((((kl >> 3)) ^ (arow & 7)) << 4);
                uint32_t ah[4], al[4];
                ldsm4(ah, pA); ldsm4(al, pA + 8192);
                int kg = kt * 64 + ks * 16 + bkh;
                const char* pB = smem + WZR_OFF + bn1 * 2048 + (((kg >> 3) ^ (bn1 & 7)) << 4);
                uint32_t bh[4], bl[4];
                ldsm4(bh, pB); ldsm4(bl, pB + 65536);
                mma16816(acc1[0], ah, bh); mma16816(acc1[1], ah, bh + 2);
                mma16816(acc1[0], ah, bl); mma16816(acc1[1], ah, bl + 2);
                mma16816(acc1[0], al, bh); mma16816(acc1[1], al, bh + 2);
            }
            __syncthreads();
        }

        // ---- act1: z -> g_z ; r -> (r*h) splits into g_A2 ----
        #pragma unroll
        for (int nf = 0; nf < 2; nf++) {
            #pragma unroll
            for (int e = 0; e < 4; e++) {
                int col = nt * 16 + nf * 8 + ecol[e];
                float pre = acc1[nf][e] + xp1[nf][e];
                float s = 1.f / (1.f + expf(-pre));
                if (wsel) {           // r-warps
                    float rh = s * hpre[nf][e];
                    bf16 hi, lo; split2(rh, hi, lo);
                    char* p = (char*)g_A2 + aoff(erow[e], col);
                    *(bf16*)p = hi;
                    *(bf16*)(p + 8192) = lo;
                } else {              // z-warps
                    g_z[erow[e] * Hn + col] = s;
                }
            }
        }
        bt += GRID_P; grid_bar(bt);

        // ================= phase 2: pre_t = (r*h) @ Wt^T =================
        float acc2[4] = {0.f, 0.f, 0.f, 0.f};
        issue_tile((const char*)g_A2, 0, 0);

        // prefetch epilogue operands (own-CTA cols; ordered by grid_bar/syncthreads)
        float xp2[4], zpre[4], hpre2[4];
        #pragma unroll
        for (int e = 0; e < 4; e++) {
            int col = nt * 16 + wn2 + ecol[e];
            size_t xoff = (2ull * Mtot + (size_t)t * Bn + erow[e]) * Hn + col;
            xp2[e] = g_xpre[xoff];
            int gi = erow[e] * Hn + col;
            zpre[e] = g_z[gi];
            hpre2[e] = g_h[gi];
        }

        for (int kt = 0; kt < 16; kt++) {
            int buf = kt & 1;
            if (kt + 1 < 16) issue_tile((const char*)g_A2, kt + 1, buf ^ 1);
            if (buf == 0) { mbar_wait(mb_u32, p0); p0 ^= 1; }
            else         { mbar_wait(mb_u32 + 8, p1); p1 ^= 1; }
            #pragma unroll
            for (int ks = 0; ks < 4; ks++) {
                int kl = ks * 16 + akh;
                const char* pA = smem + SA_OFF + buf * 16384 + arow * 128 + ((((kl >> 3)) ^ (arow & 7)) << 4);
                uint32_t ah[4], al[4];
                ldsm4(ah, pA); ldsm4(al, pA + 8192);
                int kg = kt * 64 + ks * 16 + bkh;
                const char* pB = smem + WT_OFF + bn2 * 2048 + (((kg >> 3) ^ (bn2 & 7)) << 4);
                uint32_t bh[2], bl[2];
                ldsm2(bh, pB); ldsm2(bl, pB + 32768);
                mma16816(acc2, ah, bh);
                mma16816(acc2, ah, bl);
                mma16816(acc2, al, bh);
            }
            __syncthreads();
        }

        // ---- act2: h update + output + h splits into g_A1 ----
        #pragma unroll
        for (int e = 0; e < 4; e++) {
            int col = nt * 16 + wn2 + ecol[e];
            float ht = tanhf(acc2[e] + xp2[e]);
            int gi = erow[e] * Hn + col;
            float z = zpre[e];
            float hn = (1.f - z) * hpre2[e] + z * ht;
            g_h[gi] = hn;
            bf16 hi, lo; split2(hn, hi, lo);
            char* p = (char*)g_A1 + aoff(erow[e], col);
            *(bf16*)p = hi;
            *(bf16*)(p + 8192) = lo;
            out[(size_t)t * (Bn * Hn) + gi] = hn;
        }
        bt += GRID_P; grid_bar(bt);
    }
}

// ---------------- launch ----------------
extern "C" void kernel_launch(void* const* d_in, const int* in_sizes, int n_in,
                              void* d_out, int out_size) {
    const float* x    = (const float*)d_in[0];
    const float* h0   = (const float*)d_in[1];
    const float* Wz_w = (const float*)d_in[2];
    const float* Wz_b = (const float*)d_in[3];
    const float* Wr_w = (const float*)d_in[4];
    const float* Wr_b = (const float*)d_in[5];
    const float* Wt_w = (const float*)d_in[6];
    const float* Wt_b = (const float*)d_in[7];
    float* out = (float*)d_out;

    cudaFuncSetAttribute(gru_persistent, cudaFuncAttributeMaxDynamicSharedMemorySize, SMEM_P);

    prep_weights<<<3072, 256>>>(Wz_w, Wr_w, Wt_w);
    prep_x<<<8192, 256>>>(x);
    prep_h<<<(Bn * Hn + 255) / 256, 256>>>(h0);
    xproj_kernel<<<dim3(24, 256), 256>>>(Wz_b, Wr_b, Wt_b);
    gru_persistent<<<GRID_P, 256, SMEM_P>>>(out);
}